// round 7
// baseline (speedup 1.0000x reference)
#include <cuda_runtime.h>
#include <math.h>

#define Bn 8
#define Tn 512
#define Dn 1024
#define Rn 4
#define Vn 2048
#define Nn (Vn*Rn*Rn)   // 32768 columns of w_vocab
#define TC 32            // t-chunks in stage-1 reduction
#define KS 16            // split-K factor for core GEMM
#define DKS (Dn/KS)      // 64 d-rows per split
#define DB 8             // d-batch depth (LDG.128 MLP)

// ---------------- scratch (no allocations allowed) ----------------
__device__ float g_partial[TC*Bn*Dn];     // [tchunk][b][d]  (1 MB)
__device__ float g_xmean[Bn*Dn];          // [b][d]
__device__ float g_corep[KS*Bn*Nn];       // split-K partials (16 MB)
__device__ float g_core[Bn*Nn];           // reduced core (1 MB)
__device__ float g_alpha[Bn*Rn];
__device__ float g_beta[Bn*Rn];
__device__ float g_lossb[Bn];

// ---------------- K1a: partial sums over T chunks ----------------
__global__ void k_partial(const float* __restrict__ x) {
    int tc = blockIdx.x, b = blockIdx.y;
    int d4 = threadIdx.x * 4;
    const float* p = x + ((size_t)(b * Tn) + tc * (Tn/TC)) * Dn + d4;
    float4 acc = make_float4(0.f, 0.f, 0.f, 0.f);
    #pragma unroll
    for (int t = 0; t < Tn/TC; t++) {
        float4 v = *(const float4*)(p + (size_t)t * Dn);
        acc.x += v.x; acc.y += v.y; acc.z += v.z; acc.w += v.w;
    }
    *(float4*)&g_partial[(tc * Bn + b) * Dn + d4] = acc;
}

// ---------------- K1b: finalize mean ----------------
__global__ void k_xmean() {
    int idx = blockIdx.x * 256 + threadIdx.x;
    float s = 0.f;
    #pragma unroll
    for (int tc = 0; tc < TC; tc++) s += g_partial[tc * (Bn*Dn) + idx];
    g_xmean[idx] = s * (1.0f / (float)Tn);
}

// ---------------- K1c: alpha/beta, fully parallel ----------------
__global__ void __launch_bounds__(1024) k_ab(const float* __restrict__ wa,
                                             const float* __restrict__ wb) {
    int mat = blockIdx.x;
    int wid = threadIdx.x >> 5;       // output index 0..31
    int lane = threadIdx.x & 31;
    int b = wid >> 2, r = wid & 3;
    const float* wm = mat ? wb : wa;
    const float* xb = g_xmean + b * Dn;
    float s = 0.f;
    #pragma unroll
    for (int j = 0; j < 32; j++) {
        int d = lane + j * 32;
        s = fmaf(xb[d], __ldg(&wm[d * Rn + r]), s);
    }
    #pragma unroll
    for (int off = 16; off >= 1; off >>= 1)
        s += __shfl_down_sync(0xffffffffu, s, off);
    if (lane == 0) {
        if (mat) g_beta[b * Rn + r] = s;
        else     g_alpha[b * Rn + r] = s;
    }
}

// ---------------- K2: split-K core GEMM, float4 n-vectorized ----------------
// grid (32, KS=16) = 512 blocks, 256 threads. Thread owns 4 consecutive n.
__global__ void __launch_bounds__(256) k_gemm(const float* __restrict__ wv) {
    __shared__ float xs[DKS * Bn];   // xs[dd*8 + b]
    int ks = blockIdx.y;
    int d0 = ks * DKS;
    for (int i = threadIdx.x; i < Bn * DKS; i += 256) {
        int b = i >> 6, dd = i & (DKS-1);
        xs[dd * 8 + b] = g_xmean[b * Dn + d0 + dd];
    }
    __syncthreads();

    int n = (blockIdx.x * 256 + threadIdx.x) * 4;   // base of 4 columns
    float4 acc[8];
    #pragma unroll
    for (int b = 0; b < 8; b++) acc[b] = make_float4(0.f, 0.f, 0.f, 0.f);

    const float* w = wv + (size_t)d0 * Nn + n;
    #pragma unroll 1
    for (int du = 0; du < DKS; du += DB) {
        float4 wr[DB];
        #pragma unroll
        for (int u = 0; u < DB; u++)
            wr[u] = __ldg((const float4*)(w + (size_t)(du + u) * Nn));
        #pragma unroll
        for (int u = 0; u < DB; u++) {
            float4 xa = *(const float4*)&xs[(du + u) * 8];
            float4 xb = *(const float4*)&xs[(du + u) * 8 + 4];
            float4 wv4 = wr[u];
            acc[0].x = fmaf(xa.x, wv4.x, acc[0].x); acc[0].y = fmaf(xa.x, wv4.y, acc[0].y);
            acc[0].z = fmaf(xa.x, wv4.z, acc[0].z); acc[0].w = fmaf(xa.x, wv4.w, acc[0].w);
            acc[1].x = fmaf(xa.y, wv4.x, acc[1].x); acc[1].y = fmaf(xa.y, wv4.y, acc[1].y);
            acc[1].z = fmaf(xa.y, wv4.z, acc[1].z); acc[1].w = fmaf(xa.y, wv4.w, acc[1].w);
            acc[2].x = fmaf(xa.z, wv4.x, acc[2].x); acc[2].y = fmaf(xa.z, wv4.y, acc[2].y);
            acc[2].z = fmaf(xa.z, wv4.z, acc[2].z); acc[2].w = fmaf(xa.z, wv4.w, acc[2].w);
            acc[3].x = fmaf(xa.w, wv4.x, acc[3].x); acc[3].y = fmaf(xa.w, wv4.y, acc[3].y);
            acc[3].z = fmaf(xa.w, wv4.z, acc[3].z); acc[3].w = fmaf(xa.w, wv4.w, acc[3].w);
            acc[4].x = fmaf(xb.x, wv4.x, acc[4].x); acc[4].y = fmaf(xb.x, wv4.y, acc[4].y);
            acc[4].z = fmaf(xb.x, wv4.z, acc[4].z); acc[4].w = fmaf(xb.x, wv4.w, acc[4].w);
            acc[5].x = fmaf(xb.y, wv4.x, acc[5].x); acc[5].y = fmaf(xb.y, wv4.y, acc[5].y);
            acc[5].z = fmaf(xb.y, wv4.z, acc[5].z); acc[5].w = fmaf(xb.y, wv4.w, acc[5].w);
            acc[6].x = fmaf(xb.z, wv4.x, acc[6].x); acc[6].y = fmaf(xb.z, wv4.y, acc[6].y);
            acc[6].z = fmaf(xb.z, wv4.z, acc[6].z); acc[6].w = fmaf(xb.z, wv4.w, acc[6].w);
            acc[7].x = fmaf(xb.w, wv4.x, acc[7].x); acc[7].y = fmaf(xb.w, wv4.y, acc[7].y);
            acc[7].z = fmaf(xb.w, wv4.z, acc[7].z); acc[7].w = fmaf(xb.w, wv4.w, acc[7].w);
        }
    }
    float* o = g_corep + (size_t)ks * (Bn*Nn) + n;
    #pragma unroll
    for (int b = 0; b < 8; b++)
        *(float4*)(o + (size_t)b * Nn) = acc[b];
}

// ---------------- K2b: reduce split-K partials (full-width) ----------------
// grid 256, 256 threads: each thread one float4 of g_core, 16 independent LDGs.
__global__ void k_reduce() {
    int i4 = (blockIdx.x * 256 + threadIdx.x) * 4;
    float4 s = *(const float4*)&g_corep[i4];
    #pragma unroll
    for (int ks = 1; ks < KS; ks++) {
        float4 v = __ldg((const float4*)&g_corep[(size_t)ks * (Bn*Nn) + i4]);
        s.x += v.x; s.y += v.y; s.z += v.z; s.w += v.w;
    }
    *(float4*)&g_core[i4] = s;
}

// ---------------- K3: gather + normalize + tree + loss ----------------
#define MST 17   // smem matrix stride to break bank conflicts

__global__ void k_tt(const int* __restrict__ labels) {
    __shared__ float bufA[256 * MST];
    __shared__ float bufB[128 * MST];
    int b = blockIdx.x;
    const float* cp = g_core + (size_t)b * Nn;

    int k = threadIdx.x;          // pair index, t = 2k, 2k+1
    {
        int y0 = __ldg(&labels[b * Tn + 2 * k]);
        int y1 = __ldg(&labels[b * Tn + 2 * k + 1]);

        float4 rows[2][4];
        #pragma unroll
        for (int half = 0; half < 2; half++) {
            int y = half ? y1 : y0;
            #pragma unroll
            for (int i = 0; i < 4; i++)
                rows[half][i] = __ldg((const float4*)(cp + i * (Vn*Rn) + y * 4));
        }

        float M0[16], M1[16];
        #pragma unroll
        for (int half = 0; half < 2; half++) {
            float4 r0 = rows[half][0], r1 = rows[half][1];
            float4 r2 = rows[half][2], r3 = rows[half][3];
            r0.x = fabsf(r0.x); r0.y = fabsf(r0.y); r0.z = fabsf(r0.z); r0.w = fabsf(r0.w);
            r1.x = fabsf(r1.x); r1.y = fabsf(r1.y); r1.z = fabsf(r1.z); r1.w = fabsf(r1.w);
            r2.x = fabsf(r2.x); r2.y = fabsf(r2.y); r2.z = fabsf(r2.z); r2.w = fabsf(r2.w);
            r3.x = fabsf(r3.x); r3.y = fabsf(r3.y); r3.z = fabsf(r3.z); r3.w = fabsf(r3.w);
            float4 s = make_float4(r0.x + r1.x + r2.x + r3.x,
                                   r0.y + r1.y + r2.y + r3.y,
                                   r0.z + r1.z + r2.z + r3.z,
                                   r0.w + r1.w + r2.w + r3.w);
            float4 inv = make_float4(1.0f / s.x, 1.0f / s.y, 1.0f / s.z, 1.0f / s.w);
            float* M = half ? M1 : M0;
            M[ 0] = r0.x * inv.x; M[ 1] = r0.y * inv.y; M[ 2] = r0.z * inv.z; M[ 3] = r0.w * inv.w;
            M[ 4] = r1.x * inv.x; M[ 5] = r1.y * inv.y; M[ 6] = r1.z * inv.z; M[ 7] = r1.w * inv.w;
            M[ 8] = r2.x * inv.x; M[ 9] = r2.y * inv.y; M[10] = r2.z * inv.z; M[11] = r2.w * inv.w;
            M[12] = r3.x * inv.x; M[13] = r3.y * inv.y; M[14] = r3.z * inv.z; M[15] = r3.w * inv.w;
        }
        // C = M1 @ M0
        float* dstM = bufA + k * MST;
        #pragma unroll
        for (int i = 0; i < 4; i++) {
            float c0 = 0.f, c1 = 0.f, c2 = 0.f, c3 = 0.f;
            #pragma unroll
            for (int l = 0; l < 4; l++) {
                float a = M1[i * 4 + l];
                c0 = fmaf(a, M0[l * 4 + 0], c0);
                c1 = fmaf(a, M0[l * 4 + 1], c1);
                c2 = fmaf(a, M0[l * 4 + 2], c2);
                c3 = fmaf(a, M0[l * 4 + 3], c3);
            }
            dstM[i * 4 + 0] = c0; dstM[i * 4 + 1] = c1;
            dstM[i * 4 + 2] = c2; dstM[i * 4 + 3] = c3;
        }
    }
    __syncthreads();

    float* src = bufA;
    float* dst = bufB;
    for (int nmat = 128; nmat >= 1; nmat >>= 1) {
        for (int kk = threadIdx.x; kk < nmat; kk += 256) {
            const float* A0 = src + (2 * kk) * MST;
            const float* A1 = src + (2 * kk + 1) * MST;
            float* C = dst + kk * MST;
            #pragma unroll
            for (int i = 0; i < 4; i++) {
                float c0 = 0.f, c1 = 0.f, c2 = 0.f, c3 = 0.f;
                #pragma unroll
                for (int l = 0; l < 4; l++) {
                    float a = A1[i * 4 + l];
                    c0 = fmaf(a, A0[l * 4 + 0], c0);
                    c1 = fmaf(a, A0[l * 4 + 1], c1);
                    c2 = fmaf(a, A0[l * 4 + 2], c2);
                    c3 = fmaf(a, A0[l * 4 + 3], c3);
                }
                C[i * 4 + 0] = c0; C[i * 4 + 1] = c1;
                C[i * 4 + 2] = c2; C[i * 4 + 3] = c3;
            }
        }
        __syncthreads();
        float* tmp = src; src = dst; dst = tmp;
    }

    if (threadIdx.x == 0) {
        const float* P = src;
        float a0 = fabsf(g_alpha[b * 4 + 0]);
        float a1 = fabsf(g_alpha[b * 4 + 1]);
        float a2 = fabsf(g_alpha[b * 4 + 2]);
        float a3 = fabsf(g_alpha[b * 4 + 3]);
        float sa = a0 + a1 + a2 + a3;
        float v0 = a0 / sa, v1 = a1 / sa, v2 = a2 / sa, v3 = a3 / sa;
        float w0 = P[ 0]*v0 + P[ 1]*v1 + P[ 2]*v2 + P[ 3]*v3;
        float w1 = P[ 4]*v0 + P[ 5]*v1 + P[ 6]*v2 + P[ 7]*v3;
        float w2 = P[ 8]*v0 + P[ 9]*v1 + P[10]*v2 + P[11]*v3;
        float w3 = P[12]*v0 + P[13]*v1 + P[14]*v2 + P[15]*v3;
        float b0 = fabsf(g_beta[b * 4 + 0]);
        float b1 = fabsf(g_beta[b * 4 + 1]);
        float b2 = fabsf(g_beta[b * 4 + 2]);
        float b3 = fabsf(g_beta[b * 4 + 3]);
        float sb = b0 + b1 + b2 + b3;
        float prob = (b0 * w0 + b1 * w1 + b2 * w2 + b3 * w3) / sb;
        g_lossb[b] = -logf(prob);
    }
}

// ---------------- K5: final mean over batches ----------------
__global__ void k_final(float* __restrict__ out) {
    float s = 0.f;
    #pragma unroll
    for (int b = 0; b < Bn; b++) s += g_lossb[b];
    out[0] = s * (1.0f / (float)Bn);
}

// ---------------- launch ----------------
extern "C" void kernel_launch(void* const* d_in, const int* in_sizes, int n_in,
                              void* d_out, int out_size) {
    const float* x      = (const float*)d_in[0];  // [B,T,D] f32
    const int*   labels = (const int*)  d_in[1];  // [B,T] i32
    const float* wa     = (const float*)d_in[2];  // [D,R]
    const float* wb     = (const float*)d_in[3];  // [D,R]
    const float* wv     = (const float*)d_in[4];  // [D,V*R*R]

    k_partial<<<dim3(TC, Bn), 256>>>(x);
    k_xmean<<<32, 256>>>();
    k_ab<<<2, 1024>>>(wa, wb);
    k_gemm<<<dim3(32, KS), 256>>>(wv);
    k_reduce<<<256, 256>>>();
    k_tt<<<Bn, 256>>>(labels);
    k_final<<<1, 1>>>((float*)d_out);
}

// round 8
// speedup vs baseline: 1.0734x; 1.0734x over previous
#include <cuda_runtime.h>
#include <math.h>

#define Bn 8
#define Tn 512
#define Dn 1024
#define Rn 4
#define Vn 2048
#define Nn (Vn*Rn*Rn)   // 32768 columns of w_vocab
#define TC 32            // t-chunks in stage-1 reduction
#define KS 8             // split-K factor for core GEMM
#define DKS (Dn/KS)      // 128 d-rows per split
#define DH (DKS/2)       // 64 d-rows per half (intra-block split)
#define DB 8             // d-batch depth (LDG.128 MLP)

// ---------------- scratch (no allocations allowed) ----------------
__device__ float g_partial[TC*Bn*Dn];     // [tchunk][b][d]  (1 MB)
__device__ float g_xmean[Bn*Dn];          // [b][d]
__device__ float g_corep[KS*Bn*Nn];       // split-K partials (8 MB)
__device__ float g_core[Bn*Nn];           // reduced core (1 MB)
__device__ float g_alpha[Bn*Rn];
__device__ float g_beta[Bn*Rn];
__device__ float g_lossb[Bn];

// ---------------- K1a: partial sums over T chunks ----------------
__global__ void k_partial(const float* __restrict__ x) {
    int tc = blockIdx.x, b = blockIdx.y;
    int d4 = threadIdx.x * 4;
    const float* p = x + ((size_t)(b * Tn) + tc * (Tn/TC)) * Dn + d4;
    float4 acc = make_float4(0.f, 0.f, 0.f, 0.f);
    #pragma unroll
    for (int t = 0; t < Tn/TC; t++) {
        float4 v = *(const float4*)(p + (size_t)t * Dn);
        acc.x += v.x; acc.y += v.y; acc.z += v.z; acc.w += v.w;
    }
    *(float4*)&g_partial[(tc * Bn + b) * Dn + d4] = acc;
}

// ---------------- K1b: finalize mean ----------------
__global__ void k_xmean() {
    int idx = blockIdx.x * 256 + threadIdx.x;
    float s = 0.f;
    #pragma unroll
    for (int tc = 0; tc < TC; tc++) s += g_partial[tc * (Bn*Dn) + idx];
    g_xmean[idx] = s * (1.0f / (float)Tn);
}

// ---------------- K2: split-K core GEMM + fused alpha/beta ----------------
// grid (65, KS). blocks x<64: GEMM tile; x==64,y<2: alpha/beta.
// GEMM block: 256 thr = 128 n-threads (4 cols each, float4) x 2 d-halves.
__global__ void __launch_bounds__(256) k_gemm(const float* __restrict__ wv,
                                              const float* __restrict__ wa,
                                              const float* __restrict__ wb) {
    if (blockIdx.x == 64) {
        // alpha/beta: mat = blockIdx.y (0/1); others exit
        if (blockIdx.y >= 2) return;
        int mat = blockIdx.y;
        int o = threadIdx.x >> 3;      // 32 outputs
        int l8 = threadIdx.x & 7;
        int b = o >> 2, r = o & 3;
        const float* wm = mat ? wb : wa;
        const float* xb = g_xmean + b * Dn;
        float s = 0.f;
        #pragma unroll
        for (int j = 0; j < 128; j++) {
            int d = l8 + j * 8;
            s = fmaf(xb[d], __ldg(&wm[d * Rn + r]), s);
        }
        s += __shfl_down_sync(0xffffffffu, s, 4, 8);
        s += __shfl_down_sync(0xffffffffu, s, 2, 8);
        s += __shfl_down_sync(0xffffffffu, s, 1, 8);
        if (l8 == 0) {
            if (mat) g_beta[b * Rn + r] = s;
            else     g_alpha[b * Rn + r] = s;
        }
        return;
    }

    __shared__ float xs[DKS * Bn];       // xs[dd*8 + b], 4 KB
    __shared__ float4 red[128 * 8];      // 16 KB combine buffer
    int ks = blockIdx.y;
    int dbase = ks * DKS;
    for (int i = threadIdx.x; i < Bn * DKS; i += 256) {
        int b = i >> 7, dd = i & (DKS-1);
        xs[dd * 8 + b] = g_xmean[b * Dn + dbase + dd];
    }
    __syncthreads();

    int dh = threadIdx.x >> 7;           // 0/1 d-half
    int nt = threadIdx.x & 127;          // n-thread
    int n = (blockIdx.x * 128 + nt) * 4; // base of 4 columns
    int dho = dh * DH;                   // local d offset of this half

    float4 acc[8];
    #pragma unroll
    for (int b = 0; b < 8; b++) acc[b] = make_float4(0.f, 0.f, 0.f, 0.f);

    const float* w = wv + (size_t)(dbase + dho) * Nn + n;
    #pragma unroll 1
    for (int du = 0; du < DH; du += DB) {
        float4 wr[DB];
        #pragma unroll
        for (int u = 0; u < DB; u++)
            wr[u] = __ldg((const float4*)(w + (size_t)(du + u) * Nn));
        #pragma unroll
        for (int u = 0; u < DB; u++) {
            int dd = dho + du + u;
            float4 xa = *(const float4*)&xs[dd * 8];
            float4 xb = *(const float4*)&xs[dd * 8 + 4];
            float4 wv4 = wr[u];
            acc[0].x = fmaf(xa.x, wv4.x, acc[0].x); acc[0].y = fmaf(xa.x, wv4.y, acc[0].y);
            acc[0].z = fmaf(xa.x, wv4.z, acc[0].z); acc[0].w = fmaf(xa.x, wv4.w, acc[0].w);
            acc[1].x = fmaf(xa.y, wv4.x, acc[1].x); acc[1].y = fmaf(xa.y, wv4.y, acc[1].y);
            acc[1].z = fmaf(xa.y, wv4.z, acc[1].z); acc[1].w = fmaf(xa.y, wv4.w, acc[1].w);
            acc[2].x = fmaf(xa.z, wv4.x, acc[2].x); acc[2].y = fmaf(xa.z, wv4.y, acc[2].y);
            acc[2].z = fmaf(xa.z, wv4.z, acc[2].z); acc[2].w = fmaf(xa.z, wv4.w, acc[2].w);
            acc[3].x = fmaf(xa.w, wv4.x, acc[3].x); acc[3].y = fmaf(xa.w, wv4.y, acc[3].y);
            acc[3].z = fmaf(xa.w, wv4.z, acc[3].z); acc[3].w = fmaf(xa.w, wv4.w, acc[3].w);
            acc[4].x = fmaf(xb.x, wv4.x, acc[4].x); acc[4].y = fmaf(xb.x, wv4.y, acc[4].y);
            acc[4].z = fmaf(xb.x, wv4.z, acc[4].z); acc[4].w = fmaf(xb.x, wv4.w, acc[4].w);
            acc[5].x = fmaf(xb.y, wv4.x, acc[5].x); acc[5].y = fmaf(xb.y, wv4.y, acc[5].y);
            acc[5].z = fmaf(xb.y, wv4.z, acc[5].z); acc[5].w = fmaf(xb.y, wv4.w, acc[5].w);
            acc[6].x = fmaf(xb.z, wv4.x, acc[6].x); acc[6].y = fmaf(xb.z, wv4.y, acc[6].y);
            acc[6].z = fmaf(xb.z, wv4.z, acc[6].z); acc[6].w = fmaf(xb.z, wv4.w, acc[6].w);
            acc[7].x = fmaf(xb.w, wv4.x, acc[7].x); acc[7].y = fmaf(xb.w, wv4.y, acc[7].y);
            acc[7].z = fmaf(xb.w, wv4.z, acc[7].z); acc[7].w = fmaf(xb.w, wv4.w, acc[7].w);
        }
    }
    __syncthreads();   // xs no longer needed
    if (dh == 1) {
        #pragma unroll
        for (int b = 0; b < 8; b++) red[nt * 8 + b] = acc[b];
    }
    __syncthreads();
    if (dh == 0) {
        float* o = g_corep + (size_t)ks * (Bn*Nn) + n;
        #pragma unroll
        for (int b = 0; b < 8; b++) {
            float4 r = red[nt * 8 + b];
            acc[b].x += r.x; acc[b].y += r.y; acc[b].z += r.z; acc[b].w += r.w;
            *(float4*)(o + (size_t)b * Nn) = acc[b];
        }
    }
}

// ---------------- K2b: reduce split-K partials (full-width) ----------------
__global__ void k_reduce() {
    int i4 = (blockIdx.x * 256 + threadIdx.x) * 4;
    float4 s = *(const float4*)&g_corep[i4];
    #pragma unroll
    for (int ks = 1; ks < KS; ks++) {
        float4 v = __ldg((const float4*)&g_corep[(size_t)ks * (Bn*Nn) + i4]);
        s.x += v.x; s.y += v.y; s.z += v.z; s.w += v.w;
    }
    *(float4*)&g_core[i4] = s;
}

// ---------------- K3: gather + normalize + shfl pair + tree + loss ----------------
#define MST 17   // smem matrix stride to break bank conflicts

__global__ void __launch_bounds__(512) k_tt(const int* __restrict__ labels) {
    __shared__ float bufA[256 * MST];   // 17.4 KB
    __shared__ float bufB[128 * MST];   //  8.7 KB
    int b = blockIdx.x;
    const float* cp = g_core + (size_t)b * Nn;
    int t = threadIdx.x;                // one matrix per thread, t = 0..511

    {
        int y = __ldg(&labels[b * Tn + t]);
        float4 r0 = __ldg((const float4*)(cp + 0 * (Vn*Rn) + y * 4));
        float4 r1 = __ldg((const float4*)(cp + 1 * (Vn*Rn) + y * 4));
        float4 r2 = __ldg((const float4*)(cp + 2 * (Vn*Rn) + y * 4));
        float4 r3 = __ldg((const float4*)(cp + 3 * (Vn*Rn) + y * 4));
        r0.x = fabsf(r0.x); r0.y = fabsf(r0.y); r0.z = fabsf(r0.z); r0.w = fabsf(r0.w);
        r1.x = fabsf(r1.x); r1.y = fabsf(r1.y); r1.z = fabsf(r1.z); r1.w = fabsf(r1.w);
        r2.x = fabsf(r2.x); r2.y = fabsf(r2.y); r2.z = fabsf(r2.z); r2.w = fabsf(r2.w);
        r3.x = fabsf(r3.x); r3.y = fabsf(r3.y); r3.z = fabsf(r3.z); r3.w = fabsf(r3.w);
        float4 s = make_float4(r0.x + r1.x + r2.x + r3.x,
                               r0.y + r1.y + r2.y + r3.y,
                               r0.z + r1.z + r2.z + r3.z,
                               r0.w + r1.w + r2.w + r3.w);
        float4 inv = make_float4(1.0f / s.x, 1.0f / s.y, 1.0f / s.z, 1.0f / s.w);
        float M[16];
        M[ 0] = r0.x * inv.x; M[ 1] = r0.y * inv.y; M[ 2] = r0.z * inv.z; M[ 3] = r0.w * inv.w;
        M[ 4] = r1.x * inv.x; M[ 5] = r1.y * inv.y; M[ 6] = r1.z * inv.z; M[ 7] = r1.w * inv.w;
        M[ 8] = r2.x * inv.x; M[ 9] = r2.y * inv.y; M[10] = r2.z * inv.z; M[11] = r2.w * inv.w;
        M[12] = r3.x * inv.x; M[13] = r3.y * inv.y; M[14] = r3.z * inv.z; M[15] = r3.w * inv.w;

        // neighbor's matrix (t odd -> delivered to t-1)
        float N_[16];
        #pragma unroll
        for (int i = 0; i < 16; i++)
            N_[i] = __shfl_down_sync(0xffffffffu, M[i], 1);

        if ((t & 1) == 0) {
            // C = M_{t+1} @ M_t = N_ @ M
            float* dstM = bufA + (t >> 1) * MST;
            #pragma unroll
            for (int i = 0; i < 4; i++) {
                float c0 = 0.f, c1 = 0.f, c2 = 0.f, c3 = 0.f;
                #pragma unroll
                for (int l = 0; l < 4; l++) {
                    float a = N_[i * 4 + l];
                    c0 = fmaf(a, M[l * 4 + 0], c0);
                    c1 = fmaf(a, M[l * 4 + 1], c1);
                    c2 = fmaf(a, M[l * 4 + 2], c2);
                    c3 = fmaf(a, M[l * 4 + 3], c3);
                }
                dstM[i * 4 + 0] = c0; dstM[i * 4 + 1] = c1;
                dstM[i * 4 + 2] = c2; dstM[i * 4 + 3] = c3;
            }
        }
    }
    __syncthreads();

    float* src = bufA;
    float* dst = bufB;
    for (int nmat = 128; nmat >= 1; nmat >>= 1) {
        if (t < nmat) {
            const float* A0 = src + (2 * t) * MST;
            const float* A1 = src + (2 * t + 1) * MST;
            float* C = dst + t * MST;
            #pragma unroll
            for (int i = 0; i < 4; i++) {
                float c0 = 0.f, c1 = 0.f, c2 = 0.f, c3 = 0.f;
                #pragma unroll
                for (int l = 0; l < 4; l++) {
                    float a = A1[i * 4 + l];
                    c0 = fmaf(a, A0[l * 4 + 0], c0);
                    c1 = fmaf(a, A0[l * 4 + 1], c1);
                    c2 = fmaf(a, A0[l * 4 + 2], c2);
                    c3 = fmaf(a, A0[l * 4 + 3], c3);
                }
                C[i * 4 + 0] = c0; C[i * 4 + 1] = c1;
                C[i * 4 + 2] = c2; C[i * 4 + 3] = c3;
            }
        }
        __syncthreads();
        float* tmp = src; src = dst; dst = tmp;
    }

    if (t == 0) {
        const float* P = src;
        float a0 = fabsf(g_alpha[b * 4 + 0]);
        float a1 = fabsf(g_alpha[b * 4 + 1]);
        float a2 = fabsf(g_alpha[b * 4 + 2]);
        float a3 = fabsf(g_alpha[b * 4 + 3]);
        float sa = a0 + a1 + a2 + a3;
        float v0 = a0 / sa, v1 = a1 / sa, v2 = a2 / sa, v3 = a3 / sa;
        float w0 = P[ 0]*v0 + P[ 1]*v1 + P[ 2]*v2 + P[ 3]*v3;
        float w1 = P[ 4]*v0 + P[ 5]*v1 + P[ 6]*v2 + P[ 7]*v3;
        float w2 = P[ 8]*v0 + P[ 9]*v1 + P[10]*v2 + P[11]*v3;
        float w3 = P[12]*v0 + P[13]*v1 + P[14]*v2 + P[15]*v3;
        float b0 = fabsf(g_beta[b * 4 + 0]);
        float b1 = fabsf(g_beta[b * 4 + 1]);
        float b2 = fabsf(g_beta[b * 4 + 2]);
        float b3 = fabsf(g_beta[b * 4 + 3]);
        float sb = b0 + b1 + b2 + b3;
        float prob = (b0 * w0 + b1 * w1 + b2 * w2 + b3 * w3) / sb;
        g_lossb[b] = -logf(prob);
    }
}

// ---------------- K5: final mean over batches ----------------
__global__ void k_final(float* __restrict__ out) {
    float s = 0.f;
    #pragma unroll
    for (int b = 0; b < Bn; b++) s += g_lossb[b];
    out[0] = s * (1.0f / (float)Bn);
}

// ---------------- launch ----------------
extern "C" void kernel_launch(void* const* d_in, const int* in_sizes, int n_in,
                              void* d_out, int out_size) {
    const float* x      = (const float*)d_in[0];  // [B,T,D] f32
    const int*   labels = (const int*)  d_in[1];  // [B,T] i32
    const float* wa     = (const float*)d_in[2];  // [D,R]
    const float* wb     = (const float*)d_in[3];  // [D,R]
    const float* wv     = (const float*)d_in[4];  // [D,V*R*R]

    k_partial<<<dim3(TC, Bn), 256>>>(x);
    k_xmean<<<32, 256>>>();
    k_gemm<<<dim3(65, KS), 256>>>(wv, wa, wb);
    k_reduce<<<256, 256>>>();
    k_tt<<<Bn, 512>>>(labels);
    k_final<<<1, 1>>>((float*)d_out);
}

// round 9
// speedup vs baseline: 1.0740x; 1.0006x over previous
#include <cuda_runtime.h>
#include <math.h>

#define Bn 8
#define Tn 512
#define Dn 1024
#define Rn 4
#define Vn 2048
#define Nn (Vn*Rn*Rn)   // 32768 columns of w_vocab
#define TC 32            // t-chunks in stage-1 reduction
#define KS 8             // split-K factor for core GEMM
#define DKS (Dn/KS)      // 128 d-rows per split
#define DH (DKS/2)       // 64 d-rows per half (intra-block split)
#define DB 8             // d-batch depth (LDG.128 MLP)

// ---------------- scratch (no allocations allowed) ----------------
__device__ float g_partial[TC*Bn*Dn];     // [tchunk][b][d]  (1 MB)
__device__ float g_xmean[Bn*Dn];          // [b][d]
__device__ float g_corep[KS*Bn*Nn];       // split-K partials (8 MB)
__device__ float g_core[Bn*Nn];           // reduced core (1 MB)
__device__ float g_alpha[Bn*Rn];
__device__ float g_beta[Bn*Rn];
__device__ float g_lossb[Bn];

// ---------------- f32x2 helpers (sm_103a packed math) ----------------
__device__ __forceinline__ unsigned long long packx2(float s) {
    unsigned long long r;
    unsigned int u = __float_as_uint(s);
    asm("mov.b64 %0, {%1, %1};" : "=l"(r) : "r"(u));
    return r;
}
__device__ __forceinline__ void ffma2(unsigned long long& d,
                                      unsigned long long a,
                                      unsigned long long b) {
    asm("fma.rn.f32x2 %0, %1, %2, %0;" : "+l"(d) : "l"(a), "l"(b));
}
__device__ __forceinline__ float2 unpack2(unsigned long long v) {
    unsigned int lo, hi;
    asm("mov.b64 {%0, %1}, %2;" : "=r"(lo), "=r"(hi) : "l"(v));
    return make_float2(__uint_as_float(lo), __uint_as_float(hi));
}

// ---------------- K1a: partial sums over T chunks ----------------
__global__ void k_partial(const float* __restrict__ x) {
    int tc = blockIdx.x, b = blockIdx.y;
    int d4 = threadIdx.x * 4;
    const float* p = x + ((size_t)(b * Tn) + tc * (Tn/TC)) * Dn + d4;
    float4 acc = make_float4(0.f, 0.f, 0.f, 0.f);
    #pragma unroll
    for (int t = 0; t < Tn/TC; t++) {
        float4 v = *(const float4*)(p + (size_t)t * Dn);
        acc.x += v.x; acc.y += v.y; acc.z += v.z; acc.w += v.w;
    }
    *(float4*)&g_partial[(tc * Bn + b) * Dn + d4] = acc;
}

// ---------------- K1b: finalize mean ----------------
__global__ void k_xmean() {
    int idx = blockIdx.x * 256 + threadIdx.x;
    float s = 0.f;
    #pragma unroll
    for (int tc = 0; tc < TC; tc++) s += g_partial[tc * (Bn*Dn) + idx];
    g_xmean[idx] = s * (1.0f / (float)Tn);
}

// ---------------- K2: split-K core GEMM (f32x2) + fused alpha/beta ----------------
// grid (65, KS). blocks x<64: GEMM tile; x==64,y<2: alpha/beta.
// GEMM block: 256 thr = 128 n-threads (4 cols each, float4) x 2 d-halves.
__global__ void __launch_bounds__(256) k_gemm(const float* __restrict__ wv,
                                              const float* __restrict__ wa,
                                              const float* __restrict__ wb) {
    if (blockIdx.x == 64) {
        if (blockIdx.y >= 2) return;
        int mat = blockIdx.y;
        int o = threadIdx.x >> 3;      // 32 outputs
        int l8 = threadIdx.x & 7;
        int b = o >> 2, r = o & 3;
        const float* wm = mat ? wb : wa;
        const float* xb = g_xmean + b * Dn;
        float s = 0.f;
        #pragma unroll
        for (int j = 0; j < 128; j++) {
            int d = l8 + j * 8;
            s = fmaf(xb[d], __ldg(&wm[d * Rn + r]), s);
        }
        s += __shfl_down_sync(0xffffffffu, s, 4, 8);
        s += __shfl_down_sync(0xffffffffu, s, 2, 8);
        s += __shfl_down_sync(0xffffffffu, s, 1, 8);
        if (l8 == 0) {
            if (mat) g_beta[b * Rn + r] = s;
            else     g_alpha[b * Rn + r] = s;
        }
        return;
    }

    __shared__ float xs[DKS * Bn];       // xs[dd*8 + b], 4 KB (16B aligned rows)
    __shared__ float4 red[128 * 8];      // 16 KB combine buffer
    int ks = blockIdx.y;
    int dbase = ks * DKS;
    for (int i = threadIdx.x; i < Bn * DKS; i += 256) {
        int b = i >> 7, dd = i & (DKS-1);
        xs[dd * 8 + b] = g_xmean[b * Dn + dbase + dd];
    }
    __syncthreads();

    int dh = threadIdx.x >> 7;           // 0/1 d-half
    int nt = threadIdx.x & 127;          // n-thread
    int n = (blockIdx.x * 128 + nt) * 4; // base of 4 columns
    int dho = dh * DH;                   // local d offset of this half

    // acc2[pair][n]: pair p holds batches (2p, 2p+1) packed in f32x2 lanes
    unsigned long long acc2[4][4];
    #pragma unroll
    for (int p = 0; p < 4; p++)
        #pragma unroll
        for (int c = 0; c < 4; c++) acc2[p][c] = 0ull;

    const float* w = wv + (size_t)(dbase + dho) * Nn + n;
    #pragma unroll 1
    for (int du = 0; du < DH; du += DB) {
        float4 wr[DB];
        #pragma unroll
        for (int u = 0; u < DB; u++)
            wr[u] = __ldg((const float4*)(w + (size_t)(du + u) * Nn));
        #pragma unroll
        for (int u = 0; u < DB; u++) {
            int dd = dho + du + u;
            // x pairs come packed for free: xs row is b-major, 32B aligned
            ulonglong2 xp01 = *(const ulonglong2*)&xs[dd * 8];      // (b0,b1),(b2,b3)
            ulonglong2 xp23 = *(const ulonglong2*)&xs[dd * 8 + 4];  // (b4,b5),(b6,b7)
            float4 w4 = wr[u];
            unsigned long long ww0 = packx2(w4.x);
            unsigned long long ww1 = packx2(w4.y);
            unsigned long long ww2 = packx2(w4.z);
            unsigned long long ww3 = packx2(w4.w);
            ffma2(acc2[0][0], xp01.x, ww0); ffma2(acc2[0][1], xp01.x, ww1);
            ffma2(acc2[0][2], xp01.x, ww2); ffma2(acc2[0][3], xp01.x, ww3);
            ffma2(acc2[1][0], xp01.y, ww0); ffma2(acc2[1][1], xp01.y, ww1);
            ffma2(acc2[1][2], xp01.y, ww2); ffma2(acc2[1][3], xp01.y, ww3);
            ffma2(acc2[2][0], xp23.x, ww0); ffma2(acc2[2][1], xp23.x, ww1);
            ffma2(acc2[2][2], xp23.x, ww2); ffma2(acc2[2][3], xp23.x, ww3);
            ffma2(acc2[3][0], xp23.y, ww0); ffma2(acc2[3][1], xp23.y, ww1);
            ffma2(acc2[3][2], xp23.y, ww2); ffma2(acc2[3][3], xp23.y, ww3);
        }
    }

    // unpack: pair p lanes -> rows b=2p (lo) and b=2p+1 (hi)
    float4 accf[8];
    #pragma unroll
    for (int p = 0; p < 4; p++) {
        float2 c0 = unpack2(acc2[p][0]);
        float2 c1 = unpack2(acc2[p][1]);
        float2 c2 = unpack2(acc2[p][2]);
        float2 c3 = unpack2(acc2[p][3]);
        accf[2*p+0] = make_float4(c0.x, c1.x, c2.x, c3.x);
        accf[2*p+1] = make_float4(c0.y, c1.y, c2.y, c3.y);
    }

    __syncthreads();   // xs no longer needed
    if (dh == 1) {
        #pragma unroll
        for (int b = 0; b < 8; b++) red[nt * 8 + b] = accf[b];
    }
    __syncthreads();
    if (dh == 0) {
        float* o = g_corep + (size_t)ks * (Bn*Nn) + n;
        #pragma unroll
        for (int b = 0; b < 8; b++) {
            float4 r = red[nt * 8 + b];
            accf[b].x += r.x; accf[b].y += r.y; accf[b].z += r.z; accf[b].w += r.w;
            *(float4*)(o + (size_t)b * Nn) = accf[b];
        }
    }
}

// ---------------- K2b: reduce split-K partials (full-width) ----------------
__global__ void k_reduce() {
    int i4 = (blockIdx.x * 256 + threadIdx.x) * 4;
    float4 s = *(const float4*)&g_corep[i4];
    #pragma unroll
    for (int ks = 1; ks < KS; ks++) {
        float4 v = __ldg((const float4*)&g_corep[(size_t)ks * (Bn*Nn) + i4]);
        s.x += v.x; s.y += v.y; s.z += v.z; s.w += v.w;
    }
    *(float4*)&g_core[i4] = s;
}

// ---------------- K3: gather + normalize + shfl pair + tree + loss ----------------
#define MST 17   // smem matrix stride to break bank conflicts

__global__ void __launch_bounds__(512) k_tt(const int* __restrict__ labels) {
    __shared__ float bufA[256 * MST];   // 17.4 KB
    __shared__ float bufB[128 * MST];   //  8.7 KB
    int b = blockIdx.x;
    const float* cp = g_core + (size_t)b * Nn;
    int t = threadIdx.x;                // one matrix per thread, t = 0..511

    {
        int y = __ldg(&labels[b * Tn + t]);
        float4 r0 = __ldg((const float4*)(cp + 0 * (Vn*Rn) + y * 4));
        float4 r1 = __ldg((const float4*)(cp + 1 * (Vn*Rn) + y * 4));
        float4 r2 = __ldg((const float4*)(cp + 2 * (Vn*Rn) + y * 4));
        float4 r3 = __ldg((const float4*)(cp + 3 * (Vn*Rn) + y * 4));
        r0.x = fabsf(r0.x); r0.y = fabsf(r0.y); r0.z = fabsf(r0.z); r0.w = fabsf(r0.w);
        r1.x = fabsf(r1.x); r1.y = fabsf(r1.y); r1.z = fabsf(r1.z); r1.w = fabsf(r1.w);
        r2.x = fabsf(r2.x); r2.y = fabsf(r2.y); r2.z = fabsf(r2.z); r2.w = fabsf(r2.w);
        r3.x = fabsf(r3.x); r3.y = fabsf(r3.y); r3.z = fabsf(r3.z); r3.w = fabsf(r3.w);
        float4 s = make_float4(r0.x + r1.x + r2.x + r3.x,
                               r0.y + r1.y + r2.y + r3.y,
                               r0.z + r1.z + r2.z + r3.z,
                               r0.w + r1.w + r2.w + r3.w);
        float4 inv = make_float4(1.0f / s.x, 1.0f / s.y, 1.0f / s.z, 1.0f / s.w);
        float M[16];
        M[ 0] = r0.x * inv.x; M[ 1] = r0.y * inv.y; M[ 2] = r0.z * inv.z; M[ 3] = r0.w * inv.w;
        M[ 4] = r1.x * inv.x; M[ 5] = r1.y * inv.y; M[ 6] = r1.z * inv.z; M[ 7] = r1.w * inv.w;
        M[ 8] = r2.x * inv.x; M[ 9] = r2.y * inv.y; M[10] = r2.z * inv.z; M[11] = r2.w * inv.w;
        M[12] = r3.x * inv.x; M[13] = r3.y * inv.y; M[14] = r3.z * inv.z; M[15] = r3.w * inv.w;

        // neighbor's matrix (t odd -> delivered to t-1)
        float N_[16];
        #pragma unroll
        for (int i = 0; i < 16; i++)
            N_[i] = __shfl_down_sync(0xffffffffu, M[i], 1);

        if ((t & 1) == 0) {
            // C = M_{t+1} @ M_t = N_ @ M
            float* dstM = bufA + (t >> 1) * MST;
            #pragma unroll
            for (int i = 0; i < 4; i++) {
                float c0 = 0.f, c1 = 0.f, c2 = 0.f, c3 = 0.f;
                #pragma unroll
                for (int l = 0; l < 4; l++) {
                    float a = N_[i * 4 + l];
                    c0 = fmaf(a, M[l * 4 + 0], c0);
                    c1 = fmaf(a, M[l * 4 + 1], c1);
                    c2 = fmaf(a, M[l * 4 + 2], c2);
                    c3 = fmaf(a, M[l * 4 + 3], c3);
                }
                dstM[i * 4 + 0] = c0; dstM[i * 4 + 1] = c1;
                dstM[i * 4 + 2] = c2; dstM[i * 4 + 3] = c3;
            }
        }
    }
    __syncthreads();

    float* src = bufA;
    float* dst = bufB;
    for (int nmat = 128; nmat >= 1; nmat >>= 1) {
        if (t < nmat) {
            const float* A0 = src + (2 * t) * MST;
            const float* A1 = src + (2 * t + 1) * MST;
            float* C = dst + t * MST;
            #pragma unroll
            for (int i = 0; i < 4; i++) {
                float c0 = 0.f, c1 = 0.f, c2 = 0.f, c3 = 0.f;
                #pragma unroll
                for (int l = 0; l < 4; l++) {
                    float a = A1[i * 4 + l];
                    c0 = fmaf(a, A0[l * 4 + 0], c0);
                    c1 = fmaf(a, A0[l * 4 + 1], c1);
                    c2 = fmaf(a, A0[l * 4 + 2], c2);
                    c3 = fmaf(a, A0[l * 4 + 3], c3);
                }
                C[i * 4 + 0] = c0; C[i * 4 + 1] = c1;
                C[i * 4 + 2] = c2; C[i * 4 + 3] = c3;
            }
        }
        __syncthreads();
        float* tmp = src; src = dst; dst = tmp;
    }

    if (t == 0) {
        const float* P = src;
        float a0 = fabsf(g_alpha[b * 4 + 0]);
        float a1 = fabsf(g_alpha[b * 4 + 1]);
        float a2 = fabsf(g_alpha[b * 4 + 2]);
        float a3 = fabsf(g_alpha[b * 4 + 3]);
        float sa = a0 + a1 + a2 + a3;
        float v0 = a0 / sa, v1 = a1 / sa, v2 = a2 / sa, v3 = a3 / sa;
        float w0 = P[ 0]*v0 + P[ 1]*v1 + P[ 2]*v2 + P[ 3]*v3;
        float w1 = P[ 4]*v0 + P[ 5]*v1 + P[ 6]*v2 + P[ 7]*v3;
        float w2 = P[ 8]*v0 + P[ 9]*v1 + P[10]*v2 + P[11]*v3;
        float w3 = P[12]*v0 + P[13]*v1 + P[14]*v2 + P[15]*v3;
        float b0 = fabsf(g_beta[b * 4 + 0]);
        float b1 = fabsf(g_beta[b * 4 + 1]);
        float b2 = fabsf(g_beta[b * 4 + 2]);
        float b3 = fabsf(g_beta[b * 4 + 3]);
        float sb = b0 + b1 + b2 + b3;
        float prob = (b0 * w0 + b1 * w1 + b2 * w2 + b3 * w3) / sb;
        g_lossb[b] = -logf(prob);
    }
}

// ---------------- K5: final mean over batches ----------------
__global__ void k_final(float* __restrict__ out) {
    float s = 0.f;
    #pragma unroll
    for (int b = 0; b < Bn; b++) s += g_lossb[b];
    out[0] = s * (1.0f / (float)Bn);
}

// ---------------- launch ----------------
extern "C" void kernel_launch(void* const* d_in, const int* in_sizes, int n_in,
                              void* d_out, int out_size) {
    const float* x      = (const float*)d_in[0];  // [B,T,D] f32
    const int*   labels = (const int*)  d_in[1];  // [B,T] i32
    const float* wa     = (const float*)d_in[2];  // [D,R]
    const float* wb     = (const float*)d_in[3];  // [D,R]
    const float* wv     = (const float*)d_in[4];  // [D,V*R*R]

    k_partial<<<dim3(TC, Bn), 256>>>(x);
    k_xmean<<<32, 256>>>();
    k_gemm<<<dim3(65, KS), 256>>>(wv, wa, wb);
    k_reduce<<<256, 256>>>();
    k_tt<<<Bn, 512>>>(labels);
    k_final<<<1, 1>>>((float*)d_out);
}

// round 10
// speedup vs baseline: 1.1744x; 1.0935x over previous
#include <cuda_runtime.h>
#include <math.h>

#define Bn 8
#define Tn 512
#define Dn 1024
#define Rn 4
#define Vn 2048
#define Nn (Vn*Rn*Rn)   // 32768 columns of w_vocab
#define TC 32            // t-chunks in stage-1 reduction
#define KS 8             // split-K factor for core GEMM
#define DKS (Dn/KS)      // 128 d-rows per split
#define DH (DKS/2)       // 64 d-rows per half (intra-block split)
#define DB 8             // d-batch depth (LDG.128 MLP)

// ---------------- scratch (no allocations allowed) ----------------
__device__ float g_partial[TC*Bn*Dn];     // [tchunk][b][d]  (1 MB)
__device__ float g_xmean[Bn*Dn];          // [b][d]
__device__ float g_core[Bn*Nn];           // accumulated core (1 MB)
__device__ float g_alpha[Bn*Rn];
__device__ float g_beta[Bn*Rn];

// ---------------- f32x2 helpers ----------------
__device__ __forceinline__ unsigned long long packx2(float s) {
    unsigned long long r;
    unsigned int u = __float_as_uint(s);
    asm("mov.b64 %0, {%1, %1};" : "=l"(r) : "r"(u));
    return r;
}
__device__ __forceinline__ void ffma2(unsigned long long& d,
                                      unsigned long long a,
                                      unsigned long long b) {
    asm("fma.rn.f32x2 %0, %1, %2, %0;" : "+l"(d) : "l"(a), "l"(b));
}
__device__ __forceinline__ float2 unpack2(unsigned long long v) {
    unsigned int lo, hi;
    asm("mov.b64 {%0, %1}, %2;" : "=r"(lo), "=r"(hi) : "l"(v));
    return make_float2(__uint_as_float(lo), __uint_as_float(hi));
}

// ---------------- K1a: partial sums over T chunks ----------------
__global__ void k_partial(const float* __restrict__ x) {
    int tc = blockIdx.x, b = blockIdx.y;
    int d4 = threadIdx.x * 4;
    const float* p = x + ((size_t)(b * Tn) + tc * (Tn/TC)) * Dn + d4;
    float4 acc = make_float4(0.f, 0.f, 0.f, 0.f);
    #pragma unroll
    for (int t = 0; t < Tn/TC; t++) {
        float4 v = *(const float4*)(p + (size_t)t * Dn);
        acc.x += v.x; acc.y += v.y; acc.z += v.z; acc.w += v.w;
    }
    *(float4*)&g_partial[(tc * Bn + b) * Dn + d4] = acc;
}

// ---------------- K1b: finalize mean + zero g_core + zero out ----------------
// grid 288: blocks 0..31 xmean; blocks 32..287 zero g_core (float4); blk32/t0 zeroes out.
__global__ void k_xmean(float* __restrict__ out) {
    if (blockIdx.x < 32) {
        int idx = blockIdx.x * 256 + threadIdx.x;
        float s = 0.f;
        #pragma unroll
        for (int tc = 0; tc < TC; tc++) s += g_partial[tc * (Bn*Dn) + idx];
        g_xmean[idx] = s * (1.0f / (float)Tn);
    } else {
        int i4 = ((blockIdx.x - 32) * 256 + threadIdx.x) * 4;
        *(float4*)&g_core[i4] = make_float4(0.f, 0.f, 0.f, 0.f);
        if (blockIdx.x == 32 && threadIdx.x == 0) out[0] = 0.f;
    }
}

// ---------------- K2: split-K core GEMM (f32x2, atomic epilogue) + alpha/beta ----------------
// grid (65, KS). blocks x<64: GEMM tile; x==64,y<2: alpha/beta.
__global__ void __launch_bounds__(256) k_gemm(const float* __restrict__ wv,
                                              const float* __restrict__ wa,
                                              const float* __restrict__ wb) {
    if (blockIdx.x == 64) {
        if (blockIdx.y >= 2) return;
        int mat = blockIdx.y;
        int o = threadIdx.x >> 3;      // 32 outputs
        int l8 = threadIdx.x & 7;
        int b = o >> 2, r = o & 3;
        const float* wm = mat ? wb : wa;
        const float* xb = g_xmean + b * Dn;
        float s = 0.f;
        #pragma unroll
        for (int j = 0; j < 128; j++) {
            int d = l8 + j * 8;
            s = fmaf(xb[d], __ldg(&wm[d * Rn + r]), s);
        }
        s += __shfl_down_sync(0xffffffffu, s, 4, 8);
        s += __shfl_down_sync(0xffffffffu, s, 2, 8);
        s += __shfl_down_sync(0xffffffffu, s, 1, 8);
        if (l8 == 0) {
            if (mat) g_beta[b * Rn + r] = s;
            else     g_alpha[b * Rn + r] = s;
        }
        return;
    }

    __shared__ float xs[DKS * Bn];       // xs[dd*8 + b], 4 KB
    __shared__ float4 red[128 * 8];      // 16 KB combine buffer
    int ks = blockIdx.y;
    int dbase = ks * DKS;
    for (int i = threadIdx.x; i < Bn * DKS; i += 256) {
        int b = i >> 7, dd = i & (DKS-1);
        xs[dd * 8 + b] = g_xmean[b * Dn + dbase + dd];
    }
    __syncthreads();

    int dh = threadIdx.x >> 7;           // 0/1 d-half
    int nt = threadIdx.x & 127;          // n-thread
    int n = (blockIdx.x * 128 + nt) * 4; // base of 4 columns
    int dho = dh * DH;

    unsigned long long acc2[4][4];
    #pragma unroll
    for (int p = 0; p < 4; p++)
        #pragma unroll
        for (int c = 0; c < 4; c++) acc2[p][c] = 0ull;

    const float* w = wv + (size_t)(dbase + dho) * Nn + n;
    #pragma unroll 1
    for (int du = 0; du < DH; du += DB) {
        float4 wr[DB];
        #pragma unroll
        for (int u = 0; u < DB; u++)
            wr[u] = __ldcs((const float4*)(w + (size_t)(du + u) * Nn));
        #pragma unroll
        for (int u = 0; u < DB; u++) {
            int dd = dho + du + u;
            ulonglong2 xp01 = *(const ulonglong2*)&xs[dd * 8];
            ulonglong2 xp23 = *(const ulonglong2*)&xs[dd * 8 + 4];
            float4 w4 = wr[u];
            unsigned long long ww0 = packx2(w4.x);
            unsigned long long ww1 = packx2(w4.y);
            unsigned long long ww2 = packx2(w4.z);
            unsigned long long ww3 = packx2(w4.w);
            ffma2(acc2[0][0], xp01.x, ww0); ffma2(acc2[0][1], xp01.x, ww1);
            ffma2(acc2[0][2], xp01.x, ww2); ffma2(acc2[0][3], xp01.x, ww3);
            ffma2(acc2[1][0], xp01.y, ww0); ffma2(acc2[1][1], xp01.y, ww1);
            ffma2(acc2[1][2], xp01.y, ww2); ffma2(acc2[1][3], xp01.y, ww3);
            ffma2(acc2[2][0], xp23.x, ww0); ffma2(acc2[2][1], xp23.x, ww1);
            ffma2(acc2[2][2], xp23.x, ww2); ffma2(acc2[2][3], xp23.x, ww3);
            ffma2(acc2[3][0], xp23.y, ww0); ffma2(acc2[3][1], xp23.y, ww1);
            ffma2(acc2[3][2], xp23.y, ww2); ffma2(acc2[3][3], xp23.y, ww3);
        }
    }

    float4 accf[8];
    #pragma unroll
    for (int p = 0; p < 4; p++) {
        float2 c0 = unpack2(acc2[p][0]);
        float2 c1 = unpack2(acc2[p][1]);
        float2 c2 = unpack2(acc2[p][2]);
        float2 c3 = unpack2(acc2[p][3]);
        accf[2*p+0] = make_float4(c0.x, c1.x, c2.x, c3.x);
        accf[2*p+1] = make_float4(c0.y, c1.y, c2.y, c3.y);
    }

    __syncthreads();
    if (dh == 1) {
        #pragma unroll
        for (int b = 0; b < 8; b++) red[nt * 8 + b] = accf[b];
    }
    __syncthreads();
    if (dh == 0) {
        #pragma unroll
        for (int b = 0; b < 8; b++) {
            float4 r = red[nt * 8 + b];
            float* o = g_core + (size_t)b * Nn + n;
            atomicAdd(o + 0, accf[b].x + r.x);
            atomicAdd(o + 1, accf[b].y + r.y);
            atomicAdd(o + 2, accf[b].z + r.z);
            atomicAdd(o + 3, accf[b].w + r.w);
        }
    }
}

// ---------------- K3: gather + normalize + shfl pair + tree + loss ----------------
#define MST 17   // smem matrix stride to break bank conflicts

__global__ void __launch_bounds__(512) k_tt(const int* __restrict__ labels,
                                            float* __restrict__ out) {
    __shared__ float bufA[256 * MST];
    __shared__ float bufB[128 * MST];
    int b = blockIdx.x;
    const float* cp = g_core + (size_t)b * Nn;
    int t = threadIdx.x;                // one matrix per thread

    {
        int y = __ldg(&labels[b * Tn + t]);
        float4 r0 = __ldg((const float4*)(cp + 0 * (Vn*Rn) + y * 4));
        float4 r1 = __ldg((const float4*)(cp + 1 * (Vn*Rn) + y * 4));
        float4 r2 = __ldg((const float4*)(cp + 2 * (Vn*Rn) + y * 4));
        float4 r3 = __ldg((const float4*)(cp + 3 * (Vn*Rn) + y * 4));
        r0.x = fabsf(r0.x); r0.y = fabsf(r0.y); r0.z = fabsf(r0.z); r0.w = fabsf(r0.w);
        r1.x = fabsf(r1.x); r1.y = fabsf(r1.y); r1.z = fabsf(r1.z); r1.w = fabsf(r1.w);
        r2.x = fabsf(r2.x); r2.y = fabsf(r2.y); r2.z = fabsf(r2.z); r2.w = fabsf(r2.w);
        r3.x = fabsf(r3.x); r3.y = fabsf(r3.y); r3.z = fabsf(r3.z); r3.w = fabsf(r3.w);
        float4 s = make_float4(r0.x + r1.x + r2.x + r3.x,
                               r0.y + r1.y + r2.y + r3.y,
                               r0.z + r1.z + r2.z + r3.z,
                               r0.w + r1.w + r2.w + r3.w);
        float4 inv = make_float4(1.0f / s.x, 1.0f / s.y, 1.0f / s.z, 1.0f / s.w);
        float M[16];
        M[ 0] = r0.x * inv.x; M[ 1] = r0.y * inv.y; M[ 2] = r0.z * inv.z; M[ 3] = r0.w * inv.w;
        M[ 4] = r1.x * inv.x; M[ 5] = r1.y * inv.y; M[ 6] = r1.z * inv.z; M[ 7] = r1.w * inv.w;
        M[ 8] = r2.x * inv.x; M[ 9] = r2.y * inv.y; M[10] = r2.z * inv.z; M[11] = r2.w * inv.w;
        M[12] = r3.x * inv.x; M[13] = r3.y * inv.y; M[14] = r3.z * inv.z; M[15] = r3.w * inv.w;

        float N_[16];
        #pragma unroll
        for (int i = 0; i < 16; i++)
            N_[i] = __shfl_down_sync(0xffffffffu, M[i], 1);

        if ((t & 1) == 0) {
            float* dstM = bufA + (t >> 1) * MST;
            #pragma unroll
            for (int i = 0; i < 4; i++) {
                float c0 = 0.f, c1 = 0.f, c2 = 0.f, c3 = 0.f;
                #pragma unroll
                for (int l = 0; l < 4; l++) {
                    float a = N_[i * 4 + l];
                    c0 = fmaf(a, M[l * 4 + 0], c0);
                    c1 = fmaf(a, M[l * 4 + 1], c1);
                    c2 = fmaf(a, M[l * 4 + 2], c2);
                    c3 = fmaf(a, M[l * 4 + 3], c3);
                }
                dstM[i * 4 + 0] = c0; dstM[i * 4 + 1] = c1;
                dstM[i * 4 + 2] = c2; dstM[i * 4 + 3] = c3;
            }
        }
    }
    __syncthreads();

    float* src = bufA;
    float* dst = bufB;
    for (int nmat = 128; nmat >= 1; nmat >>= 1) {
        if (t < nmat) {
            const float* A0 = src + (2 * t) * MST;
            const float* A1 = src + (2 * t + 1) * MST;
            float* C = dst + t * MST;
            #pragma unroll
            for (int i = 0; i < 4; i++) {
                float c0 = 0.f, c1 = 0.f, c2 = 0.f, c3 = 0.f;
                #pragma unroll
                for (int l = 0; l < 4; l++) {
                    float a = A1[i * 4 + l];
                    c0 = fmaf(a, A0[l * 4 + 0], c0);
                    c1 = fmaf(a, A0[l * 4 + 1], c1);
                    c2 = fmaf(a, A0[l * 4 + 2], c2);
                    c3 = fmaf(a, A0[l * 4 + 3], c3);
                }
                C[i * 4 + 0] = c0; C[i * 4 + 1] = c1;
                C[i * 4 + 2] = c2; C[i * 4 + 3] = c3;
            }
        }
        __syncthreads();
        float* tmp = src; src = dst; dst = tmp;
    }

    if (t == 0) {
        const float* P = src;
        float a0 = fabsf(g_alpha[b * 4 + 0]);
        float a1 = fabsf(g_alpha[b * 4 + 1]);
        float a2 = fabsf(g_alpha[b * 4 + 2]);
        float a3 = fabsf(g_alpha[b * 4 + 3]);
        float sa = a0 + a1 + a2 + a3;
        float v0 = a0 / sa, v1 = a1 / sa, v2 = a2 / sa, v3 = a3 / sa;
        float w0 = P[ 0]*v0 + P[ 1]*v1 + P[ 2]*v2 + P[ 3]*v3;
        float w1 = P[ 4]*v0 + P[ 5]*v1 + P[ 6]*v2 + P[ 7]*v3;
        float w2 = P[ 8]*v0 + P[ 9]*v1 + P[10]*v2 + P[11]*v3;
        float w3 = P[12]*v0 + P[13]*v1 + P[14]*v2 + P[15]*v3;
        float b0 = fabsf(g_beta[b * 4 + 0]);
        float b1 = fabsf(g_beta[b * 4 + 1]);
        float b2 = fabsf(g_beta[b * 4 + 2]);
        float b3 = fabsf(g_beta[b * 4 + 3]);
        float sb = b0 + b1 + b2 + b3;
        float prob = (b0 * w0 + b1 * w1 + b2 * w2 + b3 * w3) / sb;
        atomicAdd(out, -logf(prob) * (1.0f / (float)Bn));
    }
}

// ---------------- launch ----------------
extern "C" void kernel_launch(void* const* d_in, const int* in_sizes, int n_in,
                              void* d_out, int out_size) {
    const float* x      = (const float*)d_in[0];  // [B,T,D] f32
    const int*   labels = (const int*)  d_in[1];  // [B,T] i32
    const float* wa     = (const float*)d_in[2];  // [D,R]
    const float* wb     = (const float*)d_in[3];  // [D,R]
    const float* wv     = (const float*)d_in[4];  // [D,V*R*R]

    k_partial<<<dim3(TC, Bn), 256>>>(x);
    k_xmean<<<288, 256>>>((float*)d_out);
    k_gemm<<<dim3(65, KS), 256>>>(wv, wa, wb);
    k_tt<<<Bn, 512>>>(labels, (float*)d_out);
}